// round 15
// baseline (speedup 1.0000x reference)
#include <cuda_runtime.h>
#include <math.h>

#define NN    20000
#define EE    320000
#define CC    32
#define SS    64
#define GG    64
#define NRADI 8
#define HR    64
#define OUTS  16
#define HHEAD 64
#define RCUTF 5.0f
#define TABN  2048          // table knots over r in [0, RCUT]

// ---------------- scratch (device globals) ----------------------------------
__device__ float g_tab[TABN * 64];   // radial table: [knot][li*32 + c]  (512 KB)
__device__ float g_rt[EE];           // per-edge scaled r (table coordinate)
__device__ float g_h[NN * CC];       // node features
__device__ float g_agg[NN * CC];     // message aggregation
__device__ float g_u0[SS * CC];      // layer-0 species-pure update: emb + emb@Wsc0
__device__ float g_gsum[GG];
__device__ float g_gcnt[GG];
__device__ int   g_done;

// ---------------- init: h = emb[species], agg=0, rt, u0 ---------------------
// grid covers max(NN*CC, EE) = 640000 threads.
__global__ void k_init(const int* __restrict__ species, const float* __restrict__ emb,
                       const float* __restrict__ vectors,
                       const float* __restrict__ w_sc) {
    int i = blockIdx.x * blockDim.x + threadIdx.x;
    if (i < NN * CC) {
        int n = i >> 5, c = i & 31;
        g_h[i] = emb[species[n] * CC + c];
        g_agg[i] = 0.f;
    }
    if (i < EE) {
        float vx = vectors[3 * i + 0];
        float vy = vectors[3 * i + 1];
        float vz = vectors[3 * i + 2];
        float r2 = vx * vx + vy * vy + vz * vz;
        float r  = (r2 == 0.f) ? 0.f : sqrtf(r2);
        float u  = r * ((float)(TABN - 1) / RCUTF);
        g_rt[i] = fminf(u, (float)(TABN - 1) - 1e-3f);
    }
    if (i < SS * CC) {
        // u0[s][d] = emb[s][d] + sum_c emb[s][c] * w_sc[0][s][c][d]
        int s = i >> 5, d = i & 31;
        const float* er = emb + s * CC;
        const float* wr = w_sc + s * CC * CC + d;   // w_sc[0][s][c][d], stride CC over c
        float acc = er[d];
#pragma unroll 8
        for (int c = 0; c < CC; c++) acc += er[c] * wr[c * CC];
        g_u0[i] = acc;
    }
    if (i < GG) { g_gsum[i] = 0.f; g_gcnt[i] = 0.f; }
    if (i == 0) g_done = 0;
}

// ---------------- build radial table: F(r) for TABN knots -------------------
__global__ void __launch_bounds__(128) k_table(const float* __restrict__ w_r1,
                                               const float* __restrict__ b_r1,
                                               const float* __restrict__ w_r2) {
    __shared__ float s_w1[HR * NRADI];  // transposed [j][k]
    __shared__ float s_b1[HR];
    __shared__ float s_w2[HR * 64];     // [j][d]; d<32 layer0, d>=32 layer1
    int tid = threadIdx.x;
    for (int i = tid; i < HR * NRADI; i += 128) {
        int j = i / NRADI, k = i % NRADI;
        s_w1[i] = w_r1[k * HR + j];
    }
    for (int i = tid; i < HR; i += 128) s_b1[i] = b_r1[i];
    for (int i = tid; i < HR * 64; i += 128) {
        int j = i >> 6, d = i & 63;
        int li = d >> 5;
        s_w2[i] = w_r2[(li * HR + j) * 96 + (d & 31)];
    }
    __syncthreads();

    int knot = blockIdx.x * 128 + tid;
    if (knot >= TABN) return;

    float r  = (float)knot * (RCUTF / (float)(TABN - 1));
    float rs = fmaxf(r, 1e-6f);
    float u  = fminf(r * (1.f / RCUTF), 1.f);
    float omu = 1.f - u;
    float env = omu * omu * (1.f + 2.f * u);
    float pref = 0.6324555320336759f * env / rs;  // sqrt(2/RCUT)

    float theta = (3.14159265358979323846f / RCUTF) * rs;
    float s1, c1;
    sincosf(theta, &s1, &c1);
    float twoc = 2.f * c1;
    float bes[NRADI];
    float sprev = 0.f, scur = s1;
    bes[0] = pref * scur;
#pragma unroll
    for (int k = 1; k < NRADI; k++) {
        float snext = twoc * scur - sprev;
        sprev = scur; scur = snext;
        bes[k] = pref * scur;
    }

    float acc[64];
#pragma unroll
    for (int d = 0; d < 64; d++) acc[d] = 0.f;

#pragma unroll 4
    for (int j = 0; j < HR; j++) {
        const float4* w1r = (const float4*)&s_w1[j * NRADI];
        float4 a = w1r[0], b = w1r[1];
        float t = s_b1[j]
                + bes[0] * a.x + bes[1] * a.y + bes[2] * a.z + bes[3] * a.w
                + bes[4] * b.x + bes[5] * b.y + bes[6] * b.z + bes[7] * b.w;
        float rj = t / (1.f + expf(-t));  // silu
        const float4* w2r = (const float4*)&s_w2[j * 64];
#pragma unroll
        for (int q = 0; q < 16; q++) {
            float4 w = w2r[q];
            acc[4 * q + 0] += rj * w.x;
            acc[4 * q + 1] += rj * w.y;
            acc[4 * q + 2] += rj * w.z;
            acc[4 * q + 3] += rj * w.w;
        }
    }

    float4* orow = (float4*)&g_tab[knot * 64];
#pragma unroll
    for (int q = 0; q < 16; q++)
        orow[q] = make_float4(acc[4 * q + 0], acc[4 * q + 1], acc[4 * q + 2], acc[4 * q + 3]);
}

// ---------------- message + scatter: 4 threads/edge, 2 quads each -----------
__global__ void k_msg(const int* __restrict__ senders, const int* __restrict__ receivers,
                      int li) {
    int t = blockIdx.x * blockDim.x + threadIdx.x;
    int e = t >> 2;
    if (e >= EE) return;
    int q2 = (t & 3) * 2;          // first of this thread's two quads
    float u = __ldg(&g_rt[e]);
    int i = (int)u;
    float f = u - (float)i;
    int snd = __ldg(&senders[e]);
    int rcv = __ldg(&receivers[e]);

    const float* base = g_tab + i * 64 + li * 32 + q2 * 4;
#pragma unroll
    for (int k = 0; k < 2; k++) {
        float4 v0 = __ldg((const float4*)(base + 4 * k));
        float4 v1 = __ldg((const float4*)(base + 4 * k + 64));
        float rwx = v0.x + f * (v1.x - v0.x);
        float rwy = v0.y + f * (v1.y - v0.y);
        float rwz = v0.z + f * (v1.z - v0.z);
        float rww = v0.w + f * (v1.w - v0.w);
        float4 hv = __ldg(((const float4*)g_h) + snd * 8 + q2 + k);
        float mx = rwx * hv.x, my = rwy * hv.y, mz = rwz * hv.z, mw = rww * hv.w;
        float* dst = &g_agg[rcv * CC + (q2 + k) * 4];
        asm volatile("red.global.add.v4.f32 [%0], {%1,%2,%3,%4};"
                     :: "l"(dst), "f"(mx), "f"(my), "f"(mz), "f"(mw) : "memory");
    }
}

// ---------------- layer-0 update: h = agg@Wmix0 + u0[sp]; agg = 0 -----------
__global__ void __launch_bounds__(256) k_update0(const int* __restrict__ species,
                                                 const float* __restrict__ w_mix) {
    __shared__ float s_wm[CC * CC];
    int tid = threadIdx.x;
    for (int i = tid; i < CC * CC; i += 256) s_wm[i] = w_mix[i];  // w_mix[0][0]
    __syncthreads();

    int t = blockIdx.x * 256 + tid;
    int n = t >> 5;
    if (n >= NN) return;
    int lane = t & 31;
    int g  = lane >> 3;   // c-group
    int d4 = lane & 7;    // output quad

    float aggv = g_agg[n * CC + lane];

    float ax = 0.f, ay = 0.f, az = 0.f, aw = 0.f;
#pragma unroll
    for (int cc = 0; cc < 8; cc++) {
        int c = g * 8 + cc;
        float a = __shfl_sync(0xffffffffu, aggv, c);
        float4 wmv = ((const float4*)(s_wm + c * CC))[d4];
        ax += a * wmv.x;
        ay += a * wmv.y;
        az += a * wmv.z;
        aw += a * wmv.w;
    }
#pragma unroll
    for (int off = 8; off <= 16; off <<= 1) {
        ax += __shfl_xor_sync(0xffffffffu, ax, off);
        ay += __shfl_xor_sync(0xffffffffu, ay, off);
        az += __shfl_xor_sync(0xffffffffu, az, off);
        aw += __shfl_xor_sync(0xffffffffu, aw, off);
    }
    if (g == 0) {
        int sp = __ldg(&species[n]);
        float4 uq = __ldg(((const float4*)&g_u0[sp * CC]) + d4);
        ((float4*)&g_h[n * CC])[d4] =
            make_float4(ax + uq.x, ay + uq.y, az + uq.z, aw + uq.w);
    }
    g_agg[n * CC + lane] = 0.f;   // ready for next layer
}

// ---------------- layer-1 update: h = agg@Wmix1 + h@Wsc1[sp] + h ------------
__global__ void __launch_bounds__(256) k_update1(const int* __restrict__ species,
                                                 const float* __restrict__ w_mix,
                                                 const float* __restrict__ w_sc) {
    __shared__ float s_wm[CC * CC];
    int tid = threadIdx.x;
    const float* wm = w_mix + 3 * CC * CC;  // w_mix[1][0]
    for (int i = tid; i < CC * CC; i += 256) s_wm[i] = wm[i];
    __syncthreads();

    int t = blockIdx.x * 256 + tid;
    int n = t >> 5;
    if (n >= NN) return;
    int lane = t & 31;
    int g  = lane >> 3;
    int d4 = lane & 7;
    int sp = __ldg(&species[n]);
    const float* ws = w_sc + (SS + sp) * CC * CC;   // w_sc[1][sp]

    float aggv = g_agg[n * CC + lane];
    float hv   = g_h[n * CC + lane];

    float ax = 0.f, ay = 0.f, az = 0.f, aw = 0.f;
#pragma unroll
    for (int cc = 0; cc < 8; cc++) {
        int c = g * 8 + cc;
        float a  = __shfl_sync(0xffffffffu, aggv, c);
        float hc = __shfl_sync(0xffffffffu, hv, c);
        float4 wmv = ((const float4*)(s_wm + c * CC))[d4];
        float4 wsv = __ldg(((const float4*)(ws + c * CC)) + d4);
        ax += a * wmv.x + hc * wsv.x;
        ay += a * wmv.y + hc * wsv.y;
        az += a * wmv.z + hc * wsv.z;
        aw += a * wmv.w + hc * wsv.w;
    }
#pragma unroll
    for (int off = 8; off <= 16; off <<= 1) {
        ax += __shfl_xor_sync(0xffffffffu, ax, off);
        ay += __shfl_xor_sync(0xffffffffu, ay, off);
        az += __shfl_xor_sync(0xffffffffu, az, off);
        aw += __shfl_xor_sync(0xffffffffu, aw, off);
    }
    if (g == 0) {
        float4 hq = ((const float4*)&g_h[n * CC])[d4];
        ((float4*)&g_h[n * CC])[d4] =
            make_float4(ax + hq.x, ay + hq.y, az + hq.z, aw + hq.w);
    }
}

// ---------------- readout + LN + MLP head + pooling + fused finalize --------
__device__ __forceinline__ float fast_tanh(float x) {
    float e = __expf(2.f * x);
    return 1.f - 2.f / (e + 1.f);
}

__global__ void __launch_bounds__(128) k_head(const int* __restrict__ graph_id,
                                              const float* __restrict__ w_ro,
                                              const float* __restrict__ gamma,
                                              const float* __restrict__ beta,
                                              const float* __restrict__ w_h1,
                                              const float* __restrict__ b_h1,
                                              const float* __restrict__ w_h2,
                                              const float* __restrict__ b_h2,
                                              const float* __restrict__ scale,
                                              const float* __restrict__ shift,
                                              float* __restrict__ out) {
    __shared__ float s_ro[CC * OUTS];
    __shared__ float s_h1[OUTS * HHEAD];
    __shared__ float s_h2[HHEAD];
    __shared__ float s_bh1[HHEAD];
    __shared__ float s_g[OUTS], s_b[OUTS];
    __shared__ float sbin[GG];
    __shared__ float scnt[GG];
    __shared__ int s_last;
    int tid = threadIdx.x;
    for (int i = tid; i < CC * OUTS; i += 128) s_ro[i] = w_ro[i];
    for (int i = tid; i < OUTS * HHEAD; i += 128) s_h1[i] = w_h1[i];
    for (int i = tid; i < HHEAD; i += 128) { s_h2[i] = w_h2[i]; s_bh1[i] = b_h1[i]; }
    for (int i = tid; i < OUTS; i += 128) { s_g[i] = gamma[i]; s_b[i] = beta[i]; }
    for (int i = tid; i < GG; i += 128) { sbin[i] = 0.f; scnt[i] = 0.f; }
    __syncthreads();

    int n = blockIdx.x * 128 + tid;
    if (n < NN) {
        float hrow[CC];
        const float4* hr = (const float4*)&g_h[n * CC];
#pragma unroll
        for (int q = 0; q < 8; q++) {
            float4 v = hr[q];
            hrow[4 * q + 0] = v.x; hrow[4 * q + 1] = v.y;
            hrow[4 * q + 2] = v.z; hrow[4 * q + 3] = v.w;
        }
        float ro[OUTS];
#pragma unroll
        for (int d = 0; d < OUTS; d++) {
            float s = 0.f;
#pragma unroll
            for (int c = 0; c < CC; c++) s += hrow[c] * s_ro[c * OUTS + d];
            ro[d] = s;
        }
        float mu = 0.f;
#pragma unroll
        for (int d = 0; d < OUTS; d++) mu += ro[d];
        mu *= (1.f / OUTS);
        float var = 0.f;
#pragma unroll
        for (int d = 0; d < OUTS; d++) { float x = ro[d] - mu; var += x * x; }
        var *= (1.f / OUTS);
        float inv = rsqrtf(var + 1e-6f);
        float nrm[OUTS];
#pragma unroll
        for (int d = 0; d < OUTS; d++) nrm[d] = (ro[d] - mu) * inv * s_g[d] + s_b[d];

        float outv = 0.f;
#pragma unroll 4
        for (int j = 0; j < HHEAD; j++) {
            float t2 = s_bh1[j];
#pragma unroll
            for (int d = 0; d < OUTS; d++) t2 += nrm[d] * s_h1[d * HHEAD + j];
            float x3 = t2 * t2 * t2;
            float tg = fast_tanh(0.7978845608028654f * (t2 + 0.044715f * x3));
            float gel = 0.5f * t2 * (1.f + tg);
            outv += gel * s_h2[j];
        }
        outv += b_h2[0];
        int gid = __ldg(&graph_id[n]);
        atomicAdd(&sbin[gid], outv);
        atomicAdd(&scnt[gid], 1.f);
    }
    __syncthreads();
    for (int i = tid; i < GG; i += 128) {
        if (sbin[i] != 0.f) atomicAdd(&g_gsum[i], sbin[i]);
        if (scnt[i] != 0.f) atomicAdd(&g_gcnt[i], scnt[i]);
    }

    // last-block finalization
    __threadfence();
    if (tid == 0) s_last = (atomicAdd(&g_done, 1) == (int)gridDim.x - 1);
    __syncthreads();
    if (s_last) {
        __threadfence();
        if (tid < GG) {
            float c = g_gcnt[tid];
            out[tid] = g_gsum[tid] / fmaxf(c, 1.f) * scale[0] + shift[0];
        }
    }
}

extern "C" void kernel_launch(void* const* d_in, const int* in_sizes, int n_in,
                              void* d_out, int out_size) {
    (void)in_sizes; (void)n_in; (void)out_size;
    const float* vectors   = (const float*)d_in[0];
    const int*   species   = (const int*)d_in[1];
    const int*   senders   = (const int*)d_in[2];
    const int*   receivers = (const int*)d_in[3];
    const int*   graph_id  = (const int*)d_in[4];
    const float* emb       = (const float*)d_in[5];
    const float* w_r1      = (const float*)d_in[6];
    const float* b_r1      = (const float*)d_in[7];
    const float* w_r2      = (const float*)d_in[8];
    const float* w_mix     = (const float*)d_in[9];
    const float* w_sc      = (const float*)d_in[10];
    const float* w_ro      = (const float*)d_in[11];
    const float* gamma     = (const float*)d_in[12];
    const float* beta      = (const float*)d_in[13];
    const float* w_h1      = (const float*)d_in[14];
    const float* b_h1      = (const float*)d_in[15];
    const float* w_h2      = (const float*)d_in[16];
    const float* b_h2      = (const float*)d_in[17];
    const float* scale     = (const float*)d_in[18];
    const float* shift     = (const float*)d_in[19];
    float* out = (float*)d_out;

    k_init<<<(NN * CC + 255) / 256, 256>>>(species, emb, vectors, w_sc);
    k_table<<<(TABN + 127) / 128, 128>>>(w_r1, b_r1, w_r2);
    k_msg<<<(EE * 4 + 255) / 256, 256>>>(senders, receivers, 0);
    k_update0<<<(NN * CC + 255) / 256, 256>>>(species, w_mix);
    k_msg<<<(EE * 4 + 255) / 256, 256>>>(senders, receivers, 1);
    k_update1<<<(NN * CC + 255) / 256, 256>>>(species, w_mix, w_sc);
    k_head<<<(NN + 127) / 128, 128>>>(graph_id, w_ro, gamma, beta, w_h1, b_h1, w_h2, b_h2,
                                      scale, shift, out);
}

// round 16
// speedup vs baseline: 1.1433x; 1.1433x over previous
#include <cuda_runtime.h>
#include <math.h>

#define NN    20000
#define EE    320000
#define CC    32
#define SS    64
#define GG    64
#define NRADI 8
#define HR    64
#define OUTS  16
#define HHEAD 64
#define RCUTF 5.0f
#define TABN  4096          // table knots over r in [0, RCUT]
#define NPB   64            // nodes per block in fused tail kernel

// ---------------- scratch (device globals) ----------------------------------
__device__ float g_tab[TABN * 64];   // radial table: [knot][li*32 + c]  (1 MB)
__device__ float g_rt[EE];           // per-edge scaled r (table coordinate)
__device__ float g_h[NN * CC];       // node features
__device__ float g_agg[NN * CC];     // message aggregation
__device__ float g_u0[SS * CC];      // layer-0 species-pure update: emb + emb@Wsc0
__device__ float g_gsum[GG];
__device__ float g_gcnt[GG];
__device__ int   g_done;

// ---------------- init: h = emb[species], agg=0, rt, u0 ---------------------
// grid covers max(NN*CC, EE) = 640000 threads.
__global__ void k_init(const int* __restrict__ species, const float* __restrict__ emb,
                       const float* __restrict__ vectors,
                       const float* __restrict__ w_sc) {
    int i = blockIdx.x * blockDim.x + threadIdx.x;
    if (i < NN * CC) {
        int n = i >> 5, c = i & 31;
        g_h[i] = emb[species[n] * CC + c];
        g_agg[i] = 0.f;
    }
    if (i < EE) {
        float vx = vectors[3 * i + 0];
        float vy = vectors[3 * i + 1];
        float vz = vectors[3 * i + 2];
        float r2 = vx * vx + vy * vy + vz * vz;
        float r  = (r2 == 0.f) ? 0.f : sqrtf(r2);
        float u  = r * ((float)(TABN - 1) / RCUTF);
        g_rt[i] = fminf(u, (float)(TABN - 1) - 1e-3f);
    }
    if (i < SS * CC) {
        // u0[s][d] = emb[s][d] + sum_c emb[s][c] * w_sc[0][s][c][d]
        int s = i >> 5, d = i & 31;
        const float* er = emb + s * CC;
        const float* wr = w_sc + s * CC * CC + d;   // w_sc[0][s][c][d], stride CC over c
        float acc = er[d];
#pragma unroll 8
        for (int c = 0; c < CC; c++) acc += er[c] * wr[c * CC];
        g_u0[i] = acc;
    }
    if (i < GG) { g_gsum[i] = 0.f; g_gcnt[i] = 0.f; }
    if (i == 0) g_done = 0;
}

// ---------------- build radial table: F(r) for TABN knots -------------------
__global__ void __launch_bounds__(128) k_table(const float* __restrict__ w_r1,
                                               const float* __restrict__ b_r1,
                                               const float* __restrict__ w_r2) {
    __shared__ float s_w1[HR * NRADI];  // transposed [j][k]
    __shared__ float s_b1[HR];
    __shared__ float s_w2[HR * 64];     // [j][d]; d<32 layer0, d>=32 layer1
    int tid = threadIdx.x;
    for (int i = tid; i < HR * NRADI; i += 128) {
        int j = i / NRADI, k = i % NRADI;
        s_w1[i] = w_r1[k * HR + j];
    }
    for (int i = tid; i < HR; i += 128) s_b1[i] = b_r1[i];
    for (int i = tid; i < HR * 64; i += 128) {
        int j = i >> 6, d = i & 63;
        int li = d >> 5;
        s_w2[i] = w_r2[(li * HR + j) * 96 + (d & 31)];
    }
    __syncthreads();

    int knot = blockIdx.x * 128 + tid;
    if (knot >= TABN) return;

    float r  = (float)knot * (RCUTF / (float)(TABN - 1));
    float rs = fmaxf(r, 1e-6f);
    float u  = fminf(r * (1.f / RCUTF), 1.f);
    float omu = 1.f - u;
    float env = omu * omu * (1.f + 2.f * u);
    float pref = 0.6324555320336759f * env / rs;  // sqrt(2/RCUT)

    float theta = (3.14159265358979323846f / RCUTF) * rs;
    float s1, c1;
    sincosf(theta, &s1, &c1);
    float twoc = 2.f * c1;
    float bes[NRADI];
    float sprev = 0.f, scur = s1;
    bes[0] = pref * scur;
#pragma unroll
    for (int k = 1; k < NRADI; k++) {
        float snext = twoc * scur - sprev;
        sprev = scur; scur = snext;
        bes[k] = pref * scur;
    }

    float acc[64];
#pragma unroll
    for (int d = 0; d < 64; d++) acc[d] = 0.f;

#pragma unroll 4
    for (int j = 0; j < HR; j++) {
        const float4* w1r = (const float4*)&s_w1[j * NRADI];
        float4 a = w1r[0], b = w1r[1];
        float t = s_b1[j]
                + bes[0] * a.x + bes[1] * a.y + bes[2] * a.z + bes[3] * a.w
                + bes[4] * b.x + bes[5] * b.y + bes[6] * b.z + bes[7] * b.w;
        float rj = t / (1.f + expf(-t));  // silu
        const float4* w2r = (const float4*)&s_w2[j * 64];
#pragma unroll
        for (int q = 0; q < 16; q++) {
            float4 w = w2r[q];
            acc[4 * q + 0] += rj * w.x;
            acc[4 * q + 1] += rj * w.y;
            acc[4 * q + 2] += rj * w.z;
            acc[4 * q + 3] += rj * w.w;
        }
    }

    float4* orow = (float4*)&g_tab[knot * 64];
#pragma unroll
    for (int q = 0; q < 16; q++)
        orow[q] = make_float4(acc[4 * q + 0], acc[4 * q + 1], acc[4 * q + 2], acc[4 * q + 3]);
}

// ---------------- message + scatter with fused table lookup (R11 form) ------
__global__ void k_msg(const int* __restrict__ senders, const int* __restrict__ receivers,
                      int li) {
    int t = blockIdx.x * blockDim.x + threadIdx.x;
    int e = t >> 3;
    if (e >= EE) return;
    int q = t & 7;
    float u = __ldg(&g_rt[e]);
    int i = (int)u;
    float f = u - (float)i;
    const float* base = g_tab + i * 64 + li * 32 + q * 4;
    float4 v0 = __ldg((const float4*)base);
    float4 v1 = __ldg((const float4*)(base + 64));
    float rwx = v0.x + f * (v1.x - v0.x);
    float rwy = v0.y + f * (v1.y - v0.y);
    float rwz = v0.z + f * (v1.z - v0.z);
    float rww = v0.w + f * (v1.w - v0.w);

    int snd = __ldg(&senders[e]);
    int rcv = __ldg(&receivers[e]);
    float4 hv = __ldg(((const float4*)g_h) + snd * 8 + q);
    float mx = rwx * hv.x, my = rwy * hv.y, mz = rwz * hv.z, mw = rww * hv.w;
    float* dst = &g_agg[rcv * CC + q * 4];
    asm volatile("red.global.add.v4.f32 [%0], {%1,%2,%3,%4};"
                 :: "l"(dst), "f"(mx), "f"(my), "f"(mz), "f"(mw) : "memory");
}

// ---------------- layer-0 update: h = agg@Wmix0 + u0[sp]; agg = 0 (R11) -----
__global__ void __launch_bounds__(256) k_update0(const int* __restrict__ species,
                                                 const float* __restrict__ w_mix) {
    __shared__ float s_wm[CC * CC];
    int tid = threadIdx.x;
    for (int i = tid; i < CC * CC; i += 256) s_wm[i] = w_mix[i];  // w_mix[0][0]
    __syncthreads();

    int t = blockIdx.x * 256 + tid;
    int n = t >> 5;
    if (n >= NN) return;
    int lane = t & 31;
    int g  = lane >> 3;   // c-group
    int d4 = lane & 7;    // output quad

    float aggv = g_agg[n * CC + lane];

    float ax = 0.f, ay = 0.f, az = 0.f, aw = 0.f;
#pragma unroll
    for (int cc = 0; cc < 8; cc++) {
        int c = g * 8 + cc;
        float a = __shfl_sync(0xffffffffu, aggv, c);
        float4 wmv = ((const float4*)(s_wm + c * CC))[d4];
        ax += a * wmv.x;
        ay += a * wmv.y;
        az += a * wmv.z;
        aw += a * wmv.w;
    }
#pragma unroll
    for (int off = 8; off <= 16; off <<= 1) {
        ax += __shfl_xor_sync(0xffffffffu, ax, off);
        ay += __shfl_xor_sync(0xffffffffu, ay, off);
        az += __shfl_xor_sync(0xffffffffu, az, off);
        aw += __shfl_xor_sync(0xffffffffu, aw, off);
    }
    if (g == 0) {
        int sp = __ldg(&species[n]);
        float4 uq = __ldg(((const float4*)&g_u0[sp * CC]) + d4);
        ((float4*)&g_h[n * CC])[d4] =
            make_float4(ax + uq.x, ay + uq.y, az + uq.z, aw + uq.w);
    }
    g_agg[n * CC + lane] = 0.f;
}

// ---------------- fused tail: update layer 1 + head, per 64-node block ------
// Phase 1: 8 warps x 8 nodes each compute h_new -> smem (never written to gmem).
// Phase 2: 64 threads run readout/LN/MLP/pool reading smem. Node-local fusion.
__device__ __forceinline__ float fast_tanh(float x) {
    float e = __expf(2.f * x);
    return 1.f - 2.f / (e + 1.f);
}

__global__ void __launch_bounds__(256) k_tail(const int* __restrict__ species,
                                              const float* __restrict__ w_mix,
                                              const float* __restrict__ w_sc,
                                              const int* __restrict__ graph_id,
                                              const float* __restrict__ w_ro,
                                              const float* __restrict__ gamma,
                                              const float* __restrict__ beta,
                                              const float* __restrict__ w_h1,
                                              const float* __restrict__ b_h1,
                                              const float* __restrict__ w_h2,
                                              const float* __restrict__ b_h2,
                                              const float* __restrict__ scale,
                                              const float* __restrict__ shift,
                                              float* __restrict__ out) {
    __shared__ float s_buf[1696];         // phase1: w_mix (1024); phase2: head weights
    __shared__ float s_h[NPB * 33];       // h rows, stride 33 (bank-conflict-free)
    __shared__ float sbin[GG];
    __shared__ float scnt[GG];
    __shared__ int s_last;
    int tid = threadIdx.x;

    // ---- phase 1: update layer 1 into smem ----
    {
        const float* wm = w_mix + 3 * CC * CC;  // w_mix[1][0]
        for (int i = tid; i < CC * CC; i += 256) s_buf[i] = wm[i];
    }
    __syncthreads();

    int w = tid >> 5, lane = tid & 31;
    int g  = lane >> 3;
    int d4 = lane & 7;
    int blockBase = blockIdx.x * NPB;

#pragma unroll 2
    for (int k = 0; k < 8; k++) {
        int ln = w * 8 + k;
        int n  = blockBase + ln;
        if (n < NN) {
            int sp = __ldg(&species[n]);
            const float* ws = w_sc + (SS + sp) * CC * CC;   // w_sc[1][sp]
            float aggv = g_agg[n * CC + lane];
            float hv   = g_h[n * CC + lane];

            float ax = 0.f, ay = 0.f, az = 0.f, aw = 0.f;
#pragma unroll
            for (int cc = 0; cc < 8; cc++) {
                int c = g * 8 + cc;
                float a  = __shfl_sync(0xffffffffu, aggv, c);
                float hc = __shfl_sync(0xffffffffu, hv, c);
                float4 wmv = ((const float4*)(s_buf + c * CC))[d4];
                float4 wsv = __ldg(((const float4*)(ws + c * CC)) + d4);
                ax += a * wmv.x + hc * wsv.x;
                ay += a * wmv.y + hc * wsv.y;
                az += a * wmv.z + hc * wsv.z;
                aw += a * wmv.w + hc * wsv.w;
            }
#pragma unroll
            for (int off = 8; off <= 16; off <<= 1) {
                ax += __shfl_xor_sync(0xffffffffu, ax, off);
                ay += __shfl_xor_sync(0xffffffffu, ay, off);
                az += __shfl_xor_sync(0xffffffffu, az, off);
                aw += __shfl_xor_sync(0xffffffffu, aw, off);
            }
            if (g == 0) {
                float4 hq = __ldg(((const float4*)&g_h[n * CC]) + d4);
                float* so = &s_h[ln * 33 + d4 * 4];
                so[0] = ax + hq.x;
                so[1] = ay + hq.y;
                so[2] = az + hq.z;
                so[3] = aw + hq.w;
            }
        }
    }
    __syncthreads();

    // ---- load head weights (overwrite s_buf), init pooling bins ----
    {
        float* s_ro  = s_buf;          // 512
        float* s_h1  = s_buf + 512;    // 1024
        float* s_h2  = s_buf + 1536;   // 64
        float* s_bh1 = s_buf + 1600;   // 64
        float* s_g   = s_buf + 1664;   // 16
        float* s_b   = s_buf + 1680;   // 16
        for (int i = tid; i < CC * OUTS; i += 256) s_ro[i] = w_ro[i];
        for (int i = tid; i < OUTS * HHEAD; i += 256) s_h1[i] = w_h1[i];
        for (int i = tid; i < HHEAD; i += 256) { s_h2[i] = w_h2[i]; s_bh1[i] = b_h1[i]; }
        for (int i = tid; i < OUTS; i += 256) { s_g[i] = gamma[i]; s_b[i] = beta[i]; }
        for (int i = tid; i < GG; i += 256) { sbin[i] = 0.f; scnt[i] = 0.f; }
    }
    __syncthreads();

    // ---- phase 2: head for this block's 64 nodes ----
    if (tid < NPB) {
        int n = blockBase + tid;
        if (n < NN) {
            const float* s_ro  = s_buf;
            const float* s_h1  = s_buf + 512;
            const float* s_h2  = s_buf + 1536;
            const float* s_bh1 = s_buf + 1600;
            const float* s_g   = s_buf + 1664;
            const float* s_b   = s_buf + 1680;
            const float* hrow  = &s_h[tid * 33];

            float ro[OUTS];
#pragma unroll
            for (int d = 0; d < OUTS; d++) {
                float s = 0.f;
#pragma unroll
                for (int c = 0; c < CC; c++) s += hrow[c] * s_ro[c * OUTS + d];
                ro[d] = s;
            }
            float mu = 0.f;
#pragma unroll
            for (int d = 0; d < OUTS; d++) mu += ro[d];
            mu *= (1.f / OUTS);
            float var = 0.f;
#pragma unroll
            for (int d = 0; d < OUTS; d++) { float x = ro[d] - mu; var += x * x; }
            var *= (1.f / OUTS);
            float inv = rsqrtf(var + 1e-6f);
            float nrm[OUTS];
#pragma unroll
            for (int d = 0; d < OUTS; d++) nrm[d] = (ro[d] - mu) * inv * s_g[d] + s_b[d];

            float outv = 0.f;
#pragma unroll 4
            for (int j = 0; j < HHEAD; j++) {
                float t2 = s_bh1[j];
#pragma unroll
                for (int d = 0; d < OUTS; d++) t2 += nrm[d] * s_h1[d * HHEAD + j];
                float x3 = t2 * t2 * t2;
                float tg = fast_tanh(0.7978845608028654f * (t2 + 0.044715f * x3));
                outv += 0.5f * t2 * (1.f + tg) * s_h2[j];
            }
            outv += b_h2[0];
            int gid = __ldg(&graph_id[n]);
            atomicAdd(&sbin[gid], outv);
            atomicAdd(&scnt[gid], 1.f);
        }
    }
    __syncthreads();
    for (int i = tid; i < GG; i += 256) {
        if (sbin[i] != 0.f) atomicAdd(&g_gsum[i], sbin[i]);
        if (scnt[i] != 0.f) atomicAdd(&g_gcnt[i], scnt[i]);
    }

    // ---- last-block finalization ----
    __threadfence();
    if (tid == 0) s_last = (atomicAdd(&g_done, 1) == (int)gridDim.x - 1);
    __syncthreads();
    if (s_last) {
        __threadfence();
        if (tid < GG) {
            float c = g_gcnt[tid];
            out[tid] = g_gsum[tid] / fmaxf(c, 1.f) * scale[0] + shift[0];
        }
    }
}

extern "C" void kernel_launch(void* const* d_in, const int* in_sizes, int n_in,
                              void* d_out, int out_size) {
    (void)in_sizes; (void)n_in; (void)out_size;
    const float* vectors   = (const float*)d_in[0];
    const int*   species   = (const int*)d_in[1];
    const int*   senders   = (const int*)d_in[2];
    const int*   receivers = (const int*)d_in[3];
    const int*   graph_id  = (const int*)d_in[4];
    const float* emb       = (const float*)d_in[5];
    const float* w_r1      = (const float*)d_in[6];
    const float* b_r1      = (const float*)d_in[7];
    const float* w_r2      = (const float*)d_in[8];
    const float* w_mix     = (const float*)d_in[9];
    const float* w_sc      = (const float*)d_in[10];
    const float* w_ro      = (const float*)d_in[11];
    const float* gamma     = (const float*)d_in[12];
    const float* beta      = (const float*)d_in[13];
    const float* w_h1      = (const float*)d_in[14];
    const float* b_h1      = (const float*)d_in[15];
    const float* w_h2      = (const float*)d_in[16];
    const float* b_h2      = (const float*)d_in[17];
    const float* scale     = (const float*)d_in[18];
    const float* shift     = (const float*)d_in[19];
    float* out = (float*)d_out;

    k_init<<<(NN * CC + 255) / 256, 256>>>(species, emb, vectors, w_sc);
    k_table<<<(TABN + 127) / 128, 128>>>(w_r1, b_r1, w_r2);
    k_msg<<<(EE * 8 + 255) / 256, 256>>>(senders, receivers, 0);
    k_update0<<<(NN * CC + 255) / 256, 256>>>(species, w_mix);
    k_msg<<<(EE * 8 + 255) / 256, 256>>>(senders, receivers, 1);
    k_tail<<<(NN + NPB - 1) / NPB, 256>>>(species, w_mix, w_sc, graph_id, w_ro,
                                          gamma, beta, w_h1, b_h1, w_h2, b_h2,
                                          scale, shift, out);
}